// round 2
// baseline (speedup 1.0000x reference)
#include <cuda_runtime.h>
#include <cuda_bf16.h>
#include <stdint.h>
#include <math.h>

#define BB 16
#define TT 2048
#define DD 256

// ---------------- scratch (static __device__ arrays; no runtime allocation) ----
__device__ __nv_bfloat16 g_qb[BB*TT*DD];    // q in bf16
__device__ __nv_bfloat16 g_ab[BB*TT*DD];    // a in bf16
__device__ __nv_bfloat16 g_Ut[DD*DD];       // U^T in bf16  (Ut[e][d] = U[d][e])
__device__ __nv_bfloat16 g_qU[BB*TT*DD];    // qU in bf16
__device__ unsigned      g_rmax[BB*TT];     // encoded float max per q-row
__device__ unsigned      g_cmax[BB*TT];     // encoded float max per a-row
__device__ float         g_wts[2*BB*TT];    // softmax weights (g_q then g_a)
__device__ float         g_part[2*BB*8*DD]; // pooling partials

// ---------------- helpers ----------------
__device__ __forceinline__ uint32_t smem_u32(const void* p) {
    uint32_t r;
    asm("{ .reg .u64 t; cvta.to.shared.u64 t, %1; cvt.u32.u64 %0, t; }"
        : "=r"(r) : "l"(p));
    return r;
}

__device__ __forceinline__ void cpasync16(uint32_t s, const void* g) {
    asm volatile("cp.async.cg.shared.global [%0], [%1], 16;" :: "r"(s), "l"(g) : "memory");
}
#define CP_COMMIT() asm volatile("cp.async.commit_group;" ::: "memory")
#define CP_WAIT0()  asm volatile("cp.async.wait_group 0;" ::: "memory")
#define CP_WAIT1()  asm volatile("cp.async.wait_group 1;" ::: "memory")

__device__ __forceinline__ void ldmx4(uint32_t addr, uint32_t& r0, uint32_t& r1,
                                      uint32_t& r2, uint32_t& r3) {
    asm volatile("ldmatrix.sync.aligned.m8n8.x4.shared.b16 {%0,%1,%2,%3}, [%4];"
                 : "=r"(r0), "=r"(r1), "=r"(r2), "=r"(r3) : "r"(addr));
}

__device__ __forceinline__ void mma16816(float* c, uint32_t a0, uint32_t a1,
                                         uint32_t a2, uint32_t a3,
                                         uint32_t b0, uint32_t b1) {
    asm volatile(
        "mma.sync.aligned.m16n8k16.row.col.f32.bf16.bf16.f32 "
        "{%0,%1,%2,%3}, {%4,%5,%6,%7}, {%8,%9}, {%0,%1,%2,%3};"
        : "+f"(c[0]), "+f"(c[1]), "+f"(c[2]), "+f"(c[3])
        : "r"(a0), "r"(a1), "r"(a2), "r"(a3), "r"(b0), "r"(b1));
}

// order-preserving float <-> unsigned encoding (atomicMax(unsigned) == float max)
__device__ __forceinline__ unsigned encf(float f) {
    unsigned u = __float_as_uint(f);
    return (u & 0x80000000u) ? ~u : (u | 0x80000000u);
}
__device__ __forceinline__ float decf(unsigned e) {
    unsigned u = (e & 0x80000000u) ? (e & 0x7FFFFFFFu) : ~e;
    return __uint_as_float(u);
}

// ---------------- GEMM core: C[128x128] = A[128x256] * B[128x256]^T (bf16->fp32)
// CTA: 256 threads = 8 warps (2 m-warps x 4 n-warps), warp tile 64x32.
// KC=64 double-buffered via cp.async. smem: A bufs at 0/16K, B bufs at 32K/48K.
#define GEMM_SMEM 65536

__device__ __forceinline__ void load_chunk(uint32_t smb, int buf,
                                           const __nv_bfloat16* A,
                                           const __nv_bfloat16* Bm, int ck, int tid) {
    const __nv_bfloat16* Ac = A + ck * 64;
    const __nv_bfloat16* Bc = Bm + ck * 64;
    #pragma unroll
    for (int i = 0; i < 4; i++) {
        int v = tid + i * 256;
        int row = v >> 3, kv = v & 7;
        uint32_t o = (uint32_t)row * 128u + (uint32_t)kv * 16u;
        o ^= (o >> 3) & 0x70u;
        const size_t goff = (size_t)row * DD + (size_t)kv * 8;
        cpasync16(smb + buf * 16384 + o, Ac + goff);
        cpasync16(smb + 32768 + buf * 16384 + o, Bc + goff);
    }
}

__device__ __forceinline__ void gemm_mainloop(uint32_t smb, const __nv_bfloat16* A,
                                              const __nv_bfloat16* Bm, int tid,
                                              float acc[4][4][4]) {
    const int lid = tid & 31, w = tid >> 5;
    const int wm = (w >> 2) * 64, wn = (w & 3) * 32;
    const int lrow = lid & 15;
    const uint32_t khalf = (uint32_t)(lid >> 4) * 16u;

    load_chunk(smb, 0, A, Bm, 0, tid);
    CP_COMMIT();

    #pragma unroll
    for (int ck = 0; ck < 4; ck++) {
        if (ck + 1 < 4) {
            load_chunk(smb, (ck + 1) & 1, A, Bm, ck + 1, tid);
            CP_COMMIT();
            CP_WAIT1();
        } else {
            CP_WAIT0();
        }
        __syncthreads();

        const uint32_t abase = smb + (ck & 1) * 16384;
        const uint32_t bbase = smb + 32768 + (ck & 1) * 16384;

        #pragma unroll
        for (int kk = 0; kk < 4; kk++) {
            const uint32_t koff = (uint32_t)kk * 32u + khalf;
            uint32_t a[4][4];
            #pragma unroll
            for (int mt = 0; mt < 4; mt++) {
                uint32_t o = (uint32_t)(wm + mt * 16 + lrow) * 128u + koff;
                o ^= (o >> 3) & 0x70u;
                ldmx4(abase + o, a[mt][0], a[mt][1], a[mt][2], a[mt][3]);
            }
            uint32_t b[4][2];
            #pragma unroll
            for (int np = 0; np < 2; np++) {
                uint32_t o = (uint32_t)(wn + np * 16 + lrow) * 128u + koff;
                o ^= (o >> 3) & 0x70u;
                uint32_t r0, r1, r2, r3;
                ldmx4(bbase + o, r0, r1, r2, r3);
                b[np * 2 + 0][0] = r0; b[np * 2 + 0][1] = r2;
                b[np * 2 + 1][0] = r1; b[np * 2 + 1][1] = r3;
            }
            #pragma unroll
            for (int mt = 0; mt < 4; mt++)
                #pragma unroll
                for (int nt = 0; nt < 4; nt++)
                    mma16816(acc[mt][nt], a[mt][0], a[mt][1], a[mt][2], a[mt][3],
                             b[nt][0], b[nt][1]);
        }
        __syncthreads();
    }
}

// ---------------- k0: fp32->bf16 converts, U transpose, zero max buffers ------
__global__ void k0_convert(const float* __restrict__ q, const float* __restrict__ a,
                           const float* __restrict__ U) {
    int idx = blockIdx.x * blockDim.x + threadIdx.x;
    int stride = gridDim.x * blockDim.x;
    const int NQ4 = BB * TT * DD / 4;
    for (int i = idx; i < NQ4; i += stride) {
        float4 v = ((const float4*)q)[i];
        __nv_bfloat162 lo = __floats2bfloat162_rn(v.x, v.y);
        __nv_bfloat162 hi = __floats2bfloat162_rn(v.z, v.w);
        uint2 o;
        o.x = *reinterpret_cast<unsigned*>(&lo);
        o.y = *reinterpret_cast<unsigned*>(&hi);
        ((uint2*)g_qb)[i] = o;
    }
    for (int i = idx; i < NQ4; i += stride) {
        float4 v = ((const float4*)a)[i];
        __nv_bfloat162 lo = __floats2bfloat162_rn(v.x, v.y);
        __nv_bfloat162 hi = __floats2bfloat162_rn(v.z, v.w);
        uint2 o;
        o.x = *reinterpret_cast<unsigned*>(&lo);
        o.y = *reinterpret_cast<unsigned*>(&hi);
        ((uint2*)g_ab)[i] = o;
    }
    for (int i = idx; i < DD * DD; i += stride) {
        int d = i >> 8, e = i & 255;
        g_Ut[e * DD + d] = __float2bfloat16(U[i]);
    }
    for (int i = idx; i < BB * TT; i += stride) {
        g_rmax[i] = 0u;
        g_cmax[i] = 0u;
    }
}

// ---------------- k1: qU = q @ U (via Ut rows), bf16 out ----------------------
__global__ void __launch_bounds__(256) k1_qU() {
    extern __shared__ char sm[];
    uint32_t smb = smem_u32(sm);
    int tid = threadIdx.x;
    int tileN = blockIdx.x;   // 0..1
    int tileM = blockIdx.y;   // 0..255

    float acc[4][4][4];
    #pragma unroll
    for (int i = 0; i < 4; i++)
        #pragma unroll
        for (int j = 0; j < 4; j++)
            #pragma unroll
            for (int r = 0; r < 4; r++) acc[i][j][r] = 0.0f;

    const __nv_bfloat16* A = g_qb + (size_t)tileM * 128 * DD;
    const __nv_bfloat16* Bm = g_Ut + (size_t)tileN * 128 * DD;
    gemm_mainloop(smb, A, Bm, tid, acc);

    // write bf16 output
    const int lid = tid & 31, w = tid >> 5;
    const int wm = (w >> 2) * 64, wn = (w & 3) * 32;
    const int g = lid >> 2, tg = lid & 3;
    #pragma unroll
    for (int mt = 0; mt < 4; mt++) {
        int row0 = tileM * 128 + wm + mt * 16 + g;
        #pragma unroll
        for (int nt = 0; nt < 4; nt++) {
            int col = tileN * 128 + wn + nt * 8 + 2 * tg;
            __nv_bfloat162 p0 = __floats2bfloat162_rn(acc[mt][nt][0], acc[mt][nt][1]);
            __nv_bfloat162 p1 = __floats2bfloat162_rn(acc[mt][nt][2], acc[mt][nt][3]);
            *reinterpret_cast<unsigned*>(g_qU + (size_t)row0 * DD + col) =
                *reinterpret_cast<unsigned*>(&p0);
            *reinterpret_cast<unsigned*>(g_qU + (size_t)(row0 + 8) * DD + col) =
                *reinterpret_cast<unsigned*>(&p1);
        }
    }
}

// ---------------- k2: G tile = qU_tile @ a_tile^T, fused row/col max ----------
__global__ void __launch_bounds__(256) k2_gemm_max() {
    extern __shared__ char sm[];
    uint32_t smb = smem_u32(sm);
    int tid = threadIdx.x;
    int nj = blockIdx.x;      // 0..15
    int mi = blockIdx.y;      // 0..15
    int b  = blockIdx.z;      // 0..15

    float acc[4][4][4];
    #pragma unroll
    for (int i = 0; i < 4; i++)
        #pragma unroll
        for (int j = 0; j < 4; j++)
            #pragma unroll
            for (int r = 0; r < 4; r++) acc[i][j][r] = 0.0f;

    const __nv_bfloat16* A = g_qU + ((size_t)b * TT + (size_t)mi * 128) * DD;
    const __nv_bfloat16* Bm = g_ab + ((size_t)b * TT + (size_t)nj * 128) * DD;
    gemm_mainloop(smb, A, Bm, tid, acc);

    const int lid = tid & 31, w = tid >> 5;
    const int wm = (w >> 2) * 64, wn = (w & 3) * 32;
    const int g = lid >> 2, tg = lid & 3;
    const int rowBase = b * TT + mi * 128 + wm;
    const int colBase = b * TT + nj * 128 + wn;

    // row maxes: reduce over n within thread, then over tg lanes (xor 1,2)
    #pragma unroll
    for (int mt = 0; mt < 4; mt++) {
        float r0 = -3.0e38f, r1 = -3.0e38f;
        #pragma unroll
        for (int nt = 0; nt < 4; nt++) {
            r0 = fmaxf(r0, fmaxf(acc[mt][nt][0], acc[mt][nt][1]));
            r1 = fmaxf(r1, fmaxf(acc[mt][nt][2], acc[mt][nt][3]));
        }
        r0 = fmaxf(r0, __shfl_xor_sync(0xffffffffu, r0, 1));
        r0 = fmaxf(r0, __shfl_xor_sync(0xffffffffu, r0, 2));
        r1 = fmaxf(r1, __shfl_xor_sync(0xffffffffu, r1, 1));
        r1 = fmaxf(r1, __shfl_xor_sync(0xffffffffu, r1, 2));
        if (tg == 0) {
            atomicMax(&g_rmax[rowBase + mt * 16 + g], encf(r0));
            atomicMax(&g_rmax[rowBase + mt * 16 + g + 8], encf(r1));
        }
    }
    // col maxes: reduce over m within thread, then over g lanes (xor 4,8,16)
    #pragma unroll
    for (int nt = 0; nt < 4; nt++) {
        float c0 = -3.0e38f, c1 = -3.0e38f;
        #pragma unroll
        for (int mt = 0; mt < 4; mt++) {
            c0 = fmaxf(c0, fmaxf(acc[mt][nt][0], acc[mt][nt][2]));
            c1 = fmaxf(c1, fmaxf(acc[mt][nt][1], acc[mt][nt][3]));
        }
        #pragma unroll
        for (int s = 4; s < 32; s <<= 1) {
            c0 = fmaxf(c0, __shfl_xor_sync(0xffffffffu, c0, s));
            c1 = fmaxf(c1, __shfl_xor_sync(0xffffffffu, c1, s));
        }
        if (g == 0) {
            atomicMax(&g_cmax[colBase + nt * 8 + 2 * tg], encf(c0));
            atomicMax(&g_cmax[colBase + nt * 8 + 2 * tg + 1], encf(c1));
        }
    }
}

// ---------------- k3a: tanh + softmax over T -> weights ----------------------
__global__ void k3a_weights() {
    __shared__ float red[256];
    int tid = threadIdx.x;
    int which = blockIdx.x >> 4;     // 0 = q-rows, 1 = a-rows
    int b = blockIdx.x & 15;
    const unsigned* src = (which ? g_cmax : g_rmax) + b * TT;
    float* dst = g_wts + (size_t)(which * BB + b) * TT;

    float tv[8];
    #pragma unroll
    for (int i = 0; i < 8; i++) tv[i] = tanhf(decf(src[i * 256 + tid]));

    float lm = tv[0];
    #pragma unroll
    for (int i = 1; i < 8; i++) lm = fmaxf(lm, tv[i]);
    red[tid] = lm;
    __syncthreads();
    for (int s = 128; s > 0; s >>= 1) {
        if (tid < s) red[tid] = fmaxf(red[tid], red[tid + s]);
        __syncthreads();
    }
    float mx = red[0];
    __syncthreads();

    float ls = 0.0f;
    #pragma unroll
    for (int i = 0; i < 8; i++) ls += expf(tv[i] - mx);
    red[tid] = ls;
    __syncthreads();
    for (int s = 128; s > 0; s >>= 1) {
        if (tid < s) red[tid] += red[tid + s];
        __syncthreads();
    }
    float inv = 1.0f / red[0];

    #pragma unroll
    for (int i = 0; i < 8; i++) dst[i * 256 + tid] = expf(tv[i] - mx) * inv;
}

// ---------------- k3b: weighted pooling partials ----------------------------
__global__ void k3b_pool(const float* __restrict__ q, const float* __restrict__ a) {
    __shared__ float ws[256];
    int tid = threadIdx.x;                 // = d
    int slice = blockIdx.x & 7;
    int b     = (blockIdx.x >> 3) & 15;
    int which = blockIdx.x >> 7;

    ws[tid] = g_wts[(size_t)(which * BB + b) * TT + slice * 256 + tid];
    __syncthreads();

    const float* src = which ? a : q;
    const float* base = src + ((size_t)b * TT + (size_t)slice * 256) * DD + tid;
    float acc = 0.0f;
    #pragma unroll 8
    for (int t = 0; t < 256; t++) acc += ws[t] * base[(size_t)t * DD];
    g_part[(size_t)blockIdx.x * 256 + tid] = acc;
}

// ---------------- k3c: reduce partials -> output ----------------------------
__global__ void k3c_reduce(float* __restrict__ out) {
    int i = blockIdx.x * 256 + threadIdx.x;   // 0..8191
    int which = i >> 12;
    int b = (i >> 8) & 15;
    int d = i & 255;
    size_t pb = ((size_t)(which * BB + b) * 8) * 256 + d;
    float s = 0.0f;
    #pragma unroll
    for (int k = 0; k < 8; k++) s += g_part[pb + (size_t)k * 256];
    out[i] = s;
}

// ---------------- launch ------------------------------------------------------
extern "C" void kernel_launch(void* const* d_in, const int* in_sizes, int n_in,
                              void* d_out, int out_size) {
    // metadata order is q, a, U; identify U by size for robustness
    int ui = 2;
    for (int i = 0; i < n_in; i++)
        if (in_sizes[i] == DD * DD) ui = i;
    const float* ptrs[3];
    int k = 0;
    for (int i = 0; i < n_in && k < 3; i++)
        if (i != ui) ptrs[k++] = (const float*)d_in[i];
    const float* q = ptrs[0];
    const float* a = ptrs[1];
    const float* U = (const float*)d_in[ui];
    float* out = (float*)d_out;

    static int attr_done = 0;
    if (!attr_done) {
        cudaFuncSetAttribute(k1_qU, cudaFuncAttributeMaxDynamicSharedMemorySize, GEMM_SMEM);
        cudaFuncSetAttribute(k2_gemm_max, cudaFuncAttributeMaxDynamicSharedMemorySize, GEMM_SMEM);
        attr_done = 1;
    }

    k0_convert<<<4096, 256>>>(q, a, U);
    k1_qU<<<dim3(2, 256), 256, GEMM_SMEM>>>();
    k2_gemm_max<<<dim3(16, 16, 16), 256, GEMM_SMEM>>>();
    k3a_weights<<<32, 256>>>();
    k3b_pool<<<256, 256>>>(q, a);
    k3c_reduce<<<32, 256>>>(out);
    (void)out_size;
}

// round 3
// speedup vs baseline: 1.6657x; 1.6657x over previous
#include <cuda_runtime.h>
#include <cuda_bf16.h>
#include <stdint.h>
#include <math.h>

#define BB 16
#define TT 2048
#define DD 256

// Certification threshold: computed (bf16-mma) lower bound on a row/col max.
// tanh saturates to exactly 1.0f (CUDA tanhf and XLA clamp) for x >= ~9.0;
// bf16 pipeline error is < 0.2, so a computed bound >= 9.6 certifies saturation.
#define CERT_THRESH 9.6f

// ---------------- scratch (static __device__ arrays; no runtime allocation) ----
__device__ __nv_bfloat16 g_qb[BB*TT*DD];    // q in bf16
__device__ __nv_bfloat16 g_ab[BB*TT*DD];    // a in bf16
__device__ __nv_bfloat16 g_Ut[DD*DD];       // U^T in bf16
__device__ __nv_bfloat16 g_qU[BB*TT*DD];    // qU in bf16
__device__ unsigned      g_rmax[BB*TT];     // encoded float max per q-row
__device__ unsigned      g_cmax[BB*TT];     // encoded float max per a-col
__device__ float         g_wts[2*BB*TT];    // softmax weights (fallback)
__device__ float         g_part[2*BB*8*DD]; // pooling partials (fallback)
__device__ float         g_meanpart[2*BB*16*DD]; // per-chunk mean partials
__device__ int           g_need_full;       // 0 = certified (means exact)

// ---------------- helpers ----------------
__device__ __forceinline__ uint32_t smem_u32(const void* p) {
    uint32_t r;
    asm("{ .reg .u64 t; cvta.to.shared.u64 t, %1; cvt.u32.u64 %0, t; }"
        : "=r"(r) : "l"(p));
    return r;
}

__device__ __forceinline__ void cpasync16(uint32_t s, const void* g) {
    asm volatile("cp.async.cg.shared.global [%0], [%1], 16;" :: "r"(s), "l"(g) : "memory");
}
#define CP_COMMIT() asm volatile("cp.async.commit_group;" ::: "memory")
#define CP_WAIT0()  asm volatile("cp.async.wait_group 0;" ::: "memory")
#define CP_WAIT1()  asm volatile("cp.async.wait_group 1;" ::: "memory")

__device__ __forceinline__ void ldmx4(uint32_t addr, uint32_t& r0, uint32_t& r1,
                                      uint32_t& r2, uint32_t& r3) {
    asm volatile("ldmatrix.sync.aligned.m8n8.x4.shared.b16 {%0,%1,%2,%3}, [%4];"
                 : "=r"(r0), "=r"(r1), "=r"(r2), "=r"(r3) : "r"(addr));
}

__device__ __forceinline__ void mma16816(float* c, uint32_t a0, uint32_t a1,
                                         uint32_t a2, uint32_t a3,
                                         uint32_t b0, uint32_t b1) {
    asm volatile(
        "mma.sync.aligned.m16n8k16.row.col.f32.bf16.bf16.f32 "
        "{%0,%1,%2,%3}, {%4,%5,%6,%7}, {%8,%9}, {%0,%1,%2,%3};"
        : "+f"(c[0]), "+f"(c[1]), "+f"(c[2]), "+f"(c[3])
        : "r"(a0), "r"(a1), "r"(a2), "r"(a3), "r"(b0), "r"(b1));
}

// order-preserving float <-> unsigned encoding (atomicMax(unsigned) == float max)
__device__ __forceinline__ unsigned encf(float f) {
    unsigned u = __float_as_uint(f);
    return (u & 0x80000000u) ? ~u : (u | 0x80000000u);
}
__device__ __forceinline__ float decf(unsigned e) {
    unsigned u = (e & 0x80000000u) ? (e & 0x7FFFFFFFu) : ~e;
    return __uint_as_float(u);
}

// ---------------- GEMM core: C[128x128] = A[128x256] * B[128x256]^T -----------
#define GEMM_SMEM 65536

__device__ __forceinline__ void load_chunk(uint32_t smb, int buf,
                                           const __nv_bfloat16* A,
                                           const __nv_bfloat16* Bm, int ck, int tid) {
    const __nv_bfloat16* Ac = A + ck * 64;
    const __nv_bfloat16* Bc = Bm + ck * 64;
    #pragma unroll
    for (int i = 0; i < 4; i++) {
        int v = tid + i * 256;
        int row = v >> 3, kv = v & 7;
        uint32_t o = (uint32_t)row * 128u + (uint32_t)kv * 16u;
        o ^= (o >> 3) & 0x70u;
        const size_t goff = (size_t)row * DD + (size_t)kv * 8;
        cpasync16(smb + buf * 16384 + o, Ac + goff);
        cpasync16(smb + 32768 + buf * 16384 + o, Bc + goff);
    }
}

__device__ __forceinline__ void gemm_mainloop(uint32_t smb, const __nv_bfloat16* A,
                                              const __nv_bfloat16* Bm, int tid,
                                              float acc[4][4][4]) {
    const int lid = tid & 31, w = tid >> 5;
    const int wm = (w >> 2) * 64, wn = (w & 3) * 32;
    const int lrow = lid & 15;
    const uint32_t khalf = (uint32_t)(lid >> 4) * 16u;

    load_chunk(smb, 0, A, Bm, 0, tid);
    CP_COMMIT();

    #pragma unroll
    for (int ck = 0; ck < 4; ck++) {
        if (ck + 1 < 4) {
            load_chunk(smb, (ck + 1) & 1, A, Bm, ck + 1, tid);
            CP_COMMIT();
            CP_WAIT1();
        } else {
            CP_WAIT0();
        }
        __syncthreads();

        const uint32_t abase = smb + (ck & 1) * 16384;
        const uint32_t bbase = smb + 32768 + (ck & 1) * 16384;

        #pragma unroll
        for (int kk = 0; kk < 4; kk++) {
            const uint32_t koff = (uint32_t)kk * 32u + khalf;
            uint32_t a[4][4];
            #pragma unroll
            for (int mt = 0; mt < 4; mt++) {
                uint32_t o = (uint32_t)(wm + mt * 16 + lrow) * 128u + koff;
                o ^= (o >> 3) & 0x70u;
                ldmx4(abase + o, a[mt][0], a[mt][1], a[mt][2], a[mt][3]);
            }
            uint32_t b[4][2];
            #pragma unroll
            for (int np = 0; np < 2; np++) {
                uint32_t o = (uint32_t)(wn + np * 16 + lrow) * 128u + koff;
                o ^= (o >> 3) & 0x70u;
                uint32_t r0, r1, r2, r3;
                ldmx4(bbase + o, r0, r1, r2, r3);
                b[np * 2 + 0][0] = r0; b[np * 2 + 0][1] = r2;
                b[np * 2 + 1][0] = r1; b[np * 2 + 1][1] = r3;
            }
            #pragma unroll
            for (int mt = 0; mt < 4; mt++)
                #pragma unroll
                for (int nt = 0; nt < 4; nt++)
                    mma16816(acc[mt][nt], a[mt][0], a[mt][1], a[mt][2], a[mt][3],
                             b[nt][0], b[nt][1]);
        }
        __syncthreads();
    }
}

// ---------------- k0a: fp32->bf16 convert + per-chunk mean partials -----------
// grid 512: blockIdx.x = tensor*256 + b*16 + chunk; 256 threads (thread = d)
__global__ void __launch_bounds__(256) k0a_convert_mean(const float* __restrict__ q,
                                                        const float* __restrict__ a) {
    int bx = blockIdx.x;
    int tensor = bx >> 8;
    int b = (bx >> 4) & 15;
    int chunk = bx & 15;
    int tid = threadIdx.x;

    const float* src = tensor ? a : q;
    __nv_bfloat16* dst = tensor ? g_ab : g_qb;
    size_t base = ((size_t)b * TT + (size_t)chunk * 128) * DD;

    float s = 0.0f;
    #pragma unroll 4
    for (int r = 0; r < 128; r++) {
        float v = src[base + (size_t)r * DD + tid];
        s += v;
        dst[base + (size_t)r * DD + tid] = __float2bfloat16(v);
    }
    g_meanpart[(size_t)bx * DD + tid] = s;
}

// ---------------- k0b: U transpose, zero max buffers + flag -------------------
__global__ void k0b_aux(const float* __restrict__ U) {
    int bx = blockIdx.x, tid = threadIdx.x;
    if (bx < 64) {
        // zero g_rmax (32768) and g_cmax (32768): 64 blocks * 256 thr * 4 words
        int i0 = (bx * 256 + tid) * 4;
        #pragma unroll
        for (int k = 0; k < 4; k++) {
            int i = i0 + k;
            g_rmax[i] = 0u;
            g_cmax[i] = 0u;
        }
        if (bx == 0 && tid == 0) g_need_full = 0;
    } else {
        // U transpose: 4 blocks, each 16384 elements
        int blk = bx - 64;
        #pragma unroll 4
        for (int it = 0; it < 64; it++) {
            int i = blk * 16384 + it * 256 + tid;
            int d = i >> 8, e = i & 255;
            g_Ut[e * DD + d] = __float2bfloat16(U[i]);
        }
    }
}

// ---------------- k1: qU = q @ U (via Ut rows), bf16 out ----------------------
__global__ void __launch_bounds__(256) k1_qU() {
    extern __shared__ char sm[];
    uint32_t smb = smem_u32(sm);
    int tid = threadIdx.x;
    int tileN = blockIdx.x;   // 0..1
    int tileM = blockIdx.y;   // 0..255

    float acc[4][4][4];
    #pragma unroll
    for (int i = 0; i < 4; i++)
        #pragma unroll
        for (int j = 0; j < 4; j++)
            #pragma unroll
            for (int r = 0; r < 4; r++) acc[i][j][r] = 0.0f;

    const __nv_bfloat16* A = g_qb + (size_t)tileM * 128 * DD;
    const __nv_bfloat16* Bm = g_Ut + (size_t)tileN * 128 * DD;
    gemm_mainloop(smb, A, Bm, tid, acc);

    const int lid = tid & 31, w = tid >> 5;
    const int wm = (w >> 2) * 64, wn = (w & 3) * 32;
    const int g = lid >> 2, tg = lid & 3;
    #pragma unroll
    for (int mt = 0; mt < 4; mt++) {
        int row0 = tileM * 128 + wm + mt * 16 + g;
        #pragma unroll
        for (int nt = 0; nt < 4; nt++) {
            int col = tileN * 128 + wn + nt * 8 + 2 * tg;
            __nv_bfloat162 p0 = __floats2bfloat162_rn(acc[mt][nt][0], acc[mt][nt][1]);
            __nv_bfloat162 p1 = __floats2bfloat162_rn(acc[mt][nt][2], acc[mt][nt][3]);
            *reinterpret_cast<unsigned*>(g_qU + (size_t)row0 * DD + col) =
                *reinterpret_cast<unsigned*>(&p0);
            *reinterpret_cast<unsigned*>(g_qU + (size_t)(row0 + 8) * DD + col) =
                *reinterpret_cast<unsigned*>(&p1);
        }
    }
}

// ---------------- k2: G tile GEMM with fused row/col max ----------------------
// Used both for certification slices (gated=0) and full fallback (gated=1).
__global__ void __launch_bounds__(256) k2_gemm_max(int njoff, int mioff, int gated) {
    if (gated && g_need_full == 0) return;

    extern __shared__ char sm[];
    uint32_t smb = smem_u32(sm);
    int tid = threadIdx.x;
    int nj = blockIdx.x + njoff;
    int mi = blockIdx.y + mioff;
    int b  = blockIdx.z;

    float acc[4][4][4];
    #pragma unroll
    for (int i = 0; i < 4; i++)
        #pragma unroll
        for (int j = 0; j < 4; j++)
            #pragma unroll
            for (int r = 0; r < 4; r++) acc[i][j][r] = 0.0f;

    const __nv_bfloat16* A = g_qU + ((size_t)b * TT + (size_t)mi * 128) * DD;
    const __nv_bfloat16* Bm = g_ab + ((size_t)b * TT + (size_t)nj * 128) * DD;
    gemm_mainloop(smb, A, Bm, tid, acc);

    const int lid = tid & 31, w = tid >> 5;
    const int wm = (w >> 2) * 64, wn = (w & 3) * 32;
    const int g = lid >> 2, tg = lid & 3;
    const int rowBase = b * TT + mi * 128 + wm;
    const int colBase = b * TT + nj * 128 + wn;

    #pragma unroll
    for (int mt = 0; mt < 4; mt++) {
        float r0 = -3.0e38f, r1 = -3.0e38f;
        #pragma unroll
        for (int nt = 0; nt < 4; nt++) {
            r0 = fmaxf(r0, fmaxf(acc[mt][nt][0], acc[mt][nt][1]));
            r1 = fmaxf(r1, fmaxf(acc[mt][nt][2], acc[mt][nt][3]));
        }
        r0 = fmaxf(r0, __shfl_xor_sync(0xffffffffu, r0, 1));
        r0 = fmaxf(r0, __shfl_xor_sync(0xffffffffu, r0, 2));
        r1 = fmaxf(r1, __shfl_xor_sync(0xffffffffu, r1, 1));
        r1 = fmaxf(r1, __shfl_xor_sync(0xffffffffu, r1, 2));
        if (tg == 0) {
            atomicMax(&g_rmax[rowBase + mt * 16 + g], encf(r0));
            atomicMax(&g_rmax[rowBase + mt * 16 + g + 8], encf(r1));
        }
    }
    #pragma unroll
    for (int nt = 0; nt < 4; nt++) {
        float c0 = -3.0e38f, c1 = -3.0e38f;
        #pragma unroll
        for (int mt = 0; mt < 4; mt++) {
            c0 = fmaxf(c0, fmaxf(acc[mt][nt][0], acc[mt][nt][2]));
            c1 = fmaxf(c1, fmaxf(acc[mt][nt][1], acc[mt][nt][3]));
        }
        #pragma unroll
        for (int s = 4; s < 32; s <<= 1) {
            c0 = fmaxf(c0, __shfl_xor_sync(0xffffffffu, c0, s));
            c1 = fmaxf(c1, __shfl_xor_sync(0xffffffffu, c1, s));
        }
        if (g == 0) {
            atomicMax(&g_cmax[colBase + nt * 8 + 2 * tg], encf(c0));
            atomicMax(&g_cmax[colBase + nt * 8 + 2 * tg + 1], encf(c1));
        }
    }
}

// ---------------- k_check: certify saturation of every row/col max ------------
__global__ void k_check() {
    int i = blockIdx.x * 256 + threadIdx.x;   // 0..65535
    unsigned e = (i < BB * TT) ? g_rmax[i] : g_cmax[i - BB * TT];
    if (decf(e) < CERT_THRESH) atomicOr(&g_need_full, 1);
}

// ---------------- k_out: certified path -> means ------------------------------
__global__ void k_out_mean(float* __restrict__ out) {
    if (g_need_full) return;
    int i = blockIdx.x * 256 + threadIdx.x;   // 0..8191
    int which = i >> 12;
    int b = (i >> 8) & 15;
    int d = i & 255;
    size_t pb = (size_t)(which * 256 + b * 16) * DD + d;
    float s = 0.0f;
    #pragma unroll
    for (int c = 0; c < 16; c++) s += g_meanpart[pb + (size_t)c * DD];
    out[i] = s * (1.0f / (float)TT);
}

// ---------------- fallback k3a: tanh + softmax over T -> weights --------------
__global__ void k3a_weights() {
    if (g_need_full == 0) return;
    __shared__ float red[256];
    int tid = threadIdx.x;
    int which = blockIdx.x >> 4;
    int b = blockIdx.x & 15;
    const unsigned* src = (which ? g_cmax : g_rmax) + b * TT;
    float* dst = g_wts + (size_t)(which * BB + b) * TT;

    float tv[8];
    #pragma unroll
    for (int i = 0; i < 8; i++) tv[i] = tanhf(decf(src[i * 256 + tid]));

    float lm = tv[0];
    #pragma unroll
    for (int i = 1; i < 8; i++) lm = fmaxf(lm, tv[i]);
    red[tid] = lm;
    __syncthreads();
    for (int s = 128; s > 0; s >>= 1) {
        if (tid < s) red[tid] = fmaxf(red[tid], red[tid + s]);
        __syncthreads();
    }
    float mx = red[0];
    __syncthreads();

    float ls = 0.0f;
    #pragma unroll
    for (int i = 0; i < 8; i++) ls += expf(tv[i] - mx);
    red[tid] = ls;
    __syncthreads();
    for (int s = 128; s > 0; s >>= 1) {
        if (tid < s) red[tid] += red[tid + s];
        __syncthreads();
    }
    float inv = 1.0f / red[0];

    #pragma unroll
    for (int i = 0; i < 8; i++) dst[i * 256 + tid] = expf(tv[i] - mx) * inv;
}

// ---------------- fallback k3b: weighted pooling partials ----------------------
__global__ void k3b_pool(const float* __restrict__ q, const float* __restrict__ a) {
    if (g_need_full == 0) return;
    __shared__ float ws[256];
    int tid = threadIdx.x;
    int slice = blockIdx.x & 7;
    int b     = (blockIdx.x >> 3) & 15;
    int which = blockIdx.x >> 7;

    ws[tid] = g_wts[(size_t)(which * BB + b) * TT + slice * 256 + tid];
    __syncthreads();

    const float* src = which ? a : q;
    const float* base = src + ((size_t)b * TT + (size_t)slice * 256) * DD + tid;
    float acc = 0.0f;
    #pragma unroll 8
    for (int t = 0; t < 256; t++) acc += ws[t] * base[(size_t)t * DD];
    g_part[(size_t)blockIdx.x * 256 + tid] = acc;
}

// ---------------- fallback k3c: reduce partials -> output ----------------------
__global__ void k3c_reduce(float* __restrict__ out) {
    if (g_need_full == 0) return;
    int i = blockIdx.x * 256 + threadIdx.x;
    int which = i >> 12;
    int b = (i >> 8) & 15;
    int d = i & 255;
    size_t pb = ((size_t)(which * BB + b) * 8) * 256 + d;
    float s = 0.0f;
    #pragma unroll
    for (int k = 0; k < 8; k++) s += g_part[pb + (size_t)k * 256];
    out[i] = s;
}

// ---------------- launch ------------------------------------------------------
extern "C" void kernel_launch(void* const* d_in, const int* in_sizes, int n_in,
                              void* d_out, int out_size) {
    int ui = 2;
    for (int i = 0; i < n_in; i++)
        if (in_sizes[i] == DD * DD) ui = i;
    const float* ptrs[3];
    int k = 0;
    for (int i = 0; i < n_in && k < 3; i++)
        if (i != ui) ptrs[k++] = (const float*)d_in[i];
    const float* q = ptrs[0];
    const float* a = ptrs[1];
    const float* U = (const float*)d_in[ui];
    float* out = (float*)d_out;

    static int attr_done = 0;
    if (!attr_done) {
        cudaFuncSetAttribute(k1_qU, cudaFuncAttributeMaxDynamicSharedMemorySize, GEMM_SMEM);
        cudaFuncSetAttribute(k2_gemm_max, cudaFuncAttributeMaxDynamicSharedMemorySize, GEMM_SMEM);
        attr_done = 1;
    }

    // converts + mean partials + aux init
    k0a_convert_mean<<<512, 256>>>(q, a);
    k0b_aux<<<68, 256>>>(U);
    // qU (needed by certification and by fallback)
    k1_qU<<<dim3(2, 256), 256, GEMM_SMEM>>>();
    // certification slices: rows sampled on 256 cols, cols sampled on 256 rows
    k2_gemm_max<<<dim3(2, 16, 16), 256, GEMM_SMEM>>>(0, 0, 0);
    k2_gemm_max<<<dim3(14, 2, 16), 256, GEMM_SMEM>>>(2, 0, 0);
    k_check<<<256, 256>>>();
    // certified path: write means
    k_out_mean<<<32, 256>>>(out);
    // fallback (self-disabled when certified): full exact pipeline
    k2_gemm_max<<<dim3(16, 16, 16), 256, GEMM_SMEM>>>(0, 0, 1);
    k3a_weights<<<32, 256>>>();
    k3b_pool<<<256, 256>>>(q, a);
    k3c_reduce<<<32, 256>>>(out);
    (void)out_size;
}

// round 4
// speedup vs baseline: 2.1573x; 1.2951x over previous
#include <cuda_runtime.h>
#include <cuda_bf16.h>
#include <stdint.h>
#include <math.h>

#define BB 16
#define TT 2048
#define DD 256

// Certification threshold: computed (bf16-mma) lower bound on a row/col max.
// tanh saturates to exactly 1.0f for x >= ~9.0; bf16 pipeline error << 0.6,
// so a computed bound >= 9.6 certifies saturation of that row/col max.
#define CERT_THRESH 9.6f

// ---------------- scratch (static __device__ arrays; no runtime allocation) ----
__device__ __nv_bfloat16 g_qb[BB*TT*DD];    // q in bf16
__device__ __nv_bfloat16 g_ab[BB*TT*DD];    // a in bf16
__device__ __nv_bfloat16 g_Ut[DD*DD];       // U^T in bf16
__device__ __nv_bfloat16 g_qU[BB*TT*DD];    // qU in bf16
__device__ unsigned      g_rmax[BB*TT];     // encoded float max per q-row
__device__ unsigned      g_cmax[BB*TT];     // encoded float max per a-col
__device__ float         g_wts[2*BB*TT];    // softmax weights (fallback)
__device__ float         g_part[2*BB*8*DD]; // pooling partials (fallback)
__device__ float         g_meanpart[512*4*DD]; // per-(chunk,rowgroup) mean partials
__device__ int           g_need_full;       // 0 = certified (means exact)

// ---------------- helpers ----------------
__device__ __forceinline__ uint32_t smem_u32(const void* p) {
    uint32_t r;
    asm("{ .reg .u64 t; cvta.to.shared.u64 t, %1; cvt.u32.u64 %0, t; }"
        : "=r"(r) : "l"(p));
    return r;
}

__device__ __forceinline__ void cpasync16(uint32_t s, const void* g) {
    asm volatile("cp.async.cg.shared.global [%0], [%1], 16;" :: "r"(s), "l"(g) : "memory");
}
#define CP_COMMIT() asm volatile("cp.async.commit_group;" ::: "memory")
#define CP_WAIT0()  asm volatile("cp.async.wait_group 0;" ::: "memory")

__device__ __forceinline__ void ldmx4(uint32_t addr, uint32_t& r0, uint32_t& r1,
                                      uint32_t& r2, uint32_t& r3) {
    asm volatile("ldmatrix.sync.aligned.m8n8.x4.shared.b16 {%0,%1,%2,%3}, [%4];"
                 : "=r"(r0), "=r"(r1), "=r"(r2), "=r"(r3) : "r"(addr));
}

__device__ __forceinline__ void mma16816(float* c, uint32_t a0, uint32_t a1,
                                         uint32_t a2, uint32_t a3,
                                         uint32_t b0, uint32_t b1) {
    asm volatile(
        "mma.sync.aligned.m16n8k16.row.col.f32.bf16.bf16.f32 "
        "{%0,%1,%2,%3}, {%4,%5,%6,%7}, {%8,%9}, {%0,%1,%2,%3};"
        : "+f"(c[0]), "+f"(c[1]), "+f"(c[2]), "+f"(c[3])
        : "r"(a0), "r"(a1), "r"(a2), "r"(a3), "r"(b0), "r"(b1));
}

// order-preserving float <-> unsigned encoding (atomicMax(unsigned) == float max)
__device__ __forceinline__ unsigned encf(float f) {
    unsigned u = __float_as_uint(f);
    return (u & 0x80000000u) ? ~u : (u | 0x80000000u);
}
__device__ __forceinline__ float decf(unsigned e) {
    unsigned u = (e & 0x80000000u) ? (e & 0x7FFFFFFFu) : ~e;
    return __uint_as_float(u);
}

// ---------------- GEMM core: C[128x128] = A[128x256] * B[128x256]^T -----------
#define GEMM_SMEM 65536

__device__ __forceinline__ void load_chunk(uint32_t smb, int buf,
                                           const __nv_bfloat16* __restrict__ A,
                                           const __nv_bfloat16* __restrict__ Bm,
                                           int ck, int tid) {
    const __nv_bfloat16* Ac = A + ck * 64;
    const __nv_bfloat16* Bc = Bm + ck * 64;
    #pragma unroll
    for (int i = 0; i < 4; i++) {
        int v = tid + i * 256;
        int row = v >> 3, kv = v & 7;
        uint32_t o = (uint32_t)row * 128u + (uint32_t)kv * 16u;
        o ^= (o >> 3) & 0x70u;
        const size_t goff = (size_t)row * DD + (size_t)kv * 8;
        cpasync16(smb + buf * 16384 + o, Ac + goff);
        cpasync16(smb + 32768 + buf * 16384 + o, Bc + goff);
    }
}

// Single-sync double-buffered pipeline:
//   wait(chunk ck) -> syncthreads -> prefetch ck+1 -> compute ck
// Buffer (ck+1)&1 was last read in iter ck-1, which completed before this
// iteration's barrier, so the prefetch write is race-free without a 2nd sync.
__device__ __forceinline__ void gemm_mainloop(uint32_t smb, const __nv_bfloat16* A,
                                              const __nv_bfloat16* Bm, int tid,
                                              float acc[4][4][4]) {
    const int lid = tid & 31, w = tid >> 5;
    const int wm = (w >> 2) * 64, wn = (w & 3) * 32;
    const int lrow = lid & 15;
    const uint32_t khalf = (uint32_t)(lid >> 4) * 16u;

    load_chunk(smb, 0, A, Bm, 0, tid);
    CP_COMMIT();

    #pragma unroll
    for (int ck = 0; ck < 4; ck++) {
        CP_WAIT0();
        __syncthreads();
        if (ck + 1 < 4) {
            load_chunk(smb, (ck + 1) & 1, A, Bm, ck + 1, tid);
            CP_COMMIT();
        }

        const uint32_t abase = smb + (ck & 1) * 16384;
        const uint32_t bbase = smb + 32768 + (ck & 1) * 16384;

        #pragma unroll
        for (int kk = 0; kk < 4; kk++) {
            const uint32_t koff = (uint32_t)kk * 32u + khalf;
            uint32_t a[4][4];
            #pragma unroll
            for (int mt = 0; mt < 4; mt++) {
                uint32_t o = (uint32_t)(wm + mt * 16 + lrow) * 128u + koff;
                o ^= (o >> 3) & 0x70u;
                ldmx4(abase + o, a[mt][0], a[mt][1], a[mt][2], a[mt][3]);
            }
            uint32_t b[4][2];
            #pragma unroll
            for (int np = 0; np < 2; np++) {
                uint32_t o = (uint32_t)(wn + np * 16 + lrow) * 128u + koff;
                o ^= (o >> 3) & 0x70u;
                uint32_t r0, r1, r2, r3;
                ldmx4(bbase + o, r0, r1, r2, r3);
                b[np * 2 + 0][0] = r0; b[np * 2 + 0][1] = r2;
                b[np * 2 + 1][0] = r1; b[np * 2 + 1][1] = r3;
            }
            #pragma unroll
            for (int mt = 0; mt < 4; mt++)
                #pragma unroll
                for (int nt = 0; nt < 4; nt++)
                    mma16816(acc[mt][nt], a[mt][0], a[mt][1], a[mt][2], a[mt][3],
                             b[nt][0], b[nt][1]);
        }
    }
}

// ---------------- k0: convert fp32->bf16 + mean partials + aux (merged) -------
// bx < 512 : convert; bx = tensor*256 + b*16 + chunk. Thread owns 4 d's (float4),
//            row group tid>>6, 32 row-iterations; writes per-(chunk,rowgroup) sums.
// bx >= 512: 64 blocks zero max buffers + flag; 4 blocks transpose U.
__global__ void __launch_bounds__(256) k0_convert(const float* __restrict__ q,
                                                  const float* __restrict__ a,
                                                  const float* __restrict__ U) {
    int bx = blockIdx.x;
    int tid = threadIdx.x;

    if (bx >= 512) {
        int bz = bx - 512;
        if (bz < 64) {
            int i0 = (bz * 256 + tid) * 2;
            g_rmax[i0] = 0u; g_rmax[i0 + 1] = 0u;
            g_cmax[i0] = 0u; g_cmax[i0 + 1] = 0u;
            if (bz == 0 && tid == 0) g_need_full = 0;
        } else {
            int blk = bz - 64;   // 0..3
            #pragma unroll 4
            for (int it = 0; it < 64; it++) {
                int i = blk * 16384 + it * 256 + tid;
                int d = i >> 8, e = i & 255;
                g_Ut[e * DD + d] = __float2bfloat16(U[i]);
            }
        }
        return;
    }

    int tensor = bx >> 8;
    int b = (bx >> 4) & 15;
    int chunk = bx & 15;
    const float4* src = (const float4*)((tensor ? a : q) +
                        ((size_t)b * TT + (size_t)chunk * 128) * DD);
    uint2* dst = (uint2*)((tensor ? g_ab : g_qb) +
                 ((size_t)b * TT + (size_t)chunk * 128) * DD);

    const int dvec = tid & 63;          // float4 index within row
    const int rg = tid >> 6;            // row group 0..3
    float4 s = make_float4(0.f, 0.f, 0.f, 0.f);
    #pragma unroll 4
    for (int it = 0; it < 32; it++) {
        int row = it * 4 + rg;
        float4 v = src[(size_t)row * 64 + dvec];
        s.x += v.x; s.y += v.y; s.z += v.z; s.w += v.w;
        __nv_bfloat162 lo = __floats2bfloat162_rn(v.x, v.y);
        __nv_bfloat162 hi = __floats2bfloat162_rn(v.z, v.w);
        uint2 o;
        o.x = *reinterpret_cast<unsigned*>(&lo);
        o.y = *reinterpret_cast<unsigned*>(&hi);
        dst[(size_t)row * 64 + dvec] = o;
    }
    float4* mp = (float4*)&g_meanpart[((size_t)bx * 4 + rg) * DD];
    mp[dvec] = s;
}

// ---------------- k1: qU = q @ U (via Ut rows), bf16 out ----------------------
__global__ void __launch_bounds__(256, 2) k1_qU() {
    extern __shared__ char sm[];
    uint32_t smb = smem_u32(sm);
    int tid = threadIdx.x;
    int tileN = blockIdx.x;   // 0..1
    int tileM = blockIdx.y;   // 0..255

    float acc[4][4][4];
    #pragma unroll
    for (int i = 0; i < 4; i++)
        #pragma unroll
        for (int j = 0; j < 4; j++)
            #pragma unroll
            for (int r = 0; r < 4; r++) acc[i][j][r] = 0.0f;

    const __nv_bfloat16* A = g_qb + (size_t)tileM * 128 * DD;
    const __nv_bfloat16* Bm = g_Ut + (size_t)tileN * 128 * DD;
    gemm_mainloop(smb, A, Bm, tid, acc);

    const int lid = tid & 31, w = tid >> 5;
    const int wm = (w >> 2) * 64, wn = (w & 3) * 32;
    const int g = lid >> 2, tg = lid & 3;
    #pragma unroll
    for (int mt = 0; mt < 4; mt++) {
        int row0 = tileM * 128 + wm + mt * 16 + g;
        #pragma unroll
        for (int nt = 0; nt < 4; nt++) {
            int col = tileN * 128 + wn + nt * 8 + 2 * tg;
            __nv_bfloat162 p0 = __floats2bfloat162_rn(acc[mt][nt][0], acc[mt][nt][1]);
            __nv_bfloat162 p1 = __floats2bfloat162_rn(acc[mt][nt][2], acc[mt][nt][3]);
            *reinterpret_cast<unsigned*>(g_qU + (size_t)row0 * DD + col) =
                *reinterpret_cast<unsigned*>(&p0);
            *reinterpret_cast<unsigned*>(g_qU + (size_t)(row0 + 8) * DD + col) =
                *reinterpret_cast<unsigned*>(&p1);
        }
    }
}

// ---------------- k2: G tile GEMM with fused row/col max ----------------------
__global__ void __launch_bounds__(256, 2) k2_gemm_max(int njoff, int mioff, int gated) {
    if (gated && g_need_full == 0) return;

    extern __shared__ char sm[];
    uint32_t smb = smem_u32(sm);
    int tid = threadIdx.x;
    int nj = blockIdx.x + njoff;
    int mi = blockIdx.y + mioff;
    int b  = blockIdx.z;

    float acc[4][4][4];
    #pragma unroll
    for (int i = 0; i < 4; i++)
        #pragma unroll
        for (int j = 0; j < 4; j++)
            #pragma unroll
            for (int r = 0; r < 4; r++) acc[i][j][r] = 0.0f;

    const __nv_bfloat16* A = g_qU + ((size_t)b * TT + (size_t)mi * 128) * DD;
    const __nv_bfloat16* Bm = g_ab + ((size_t)b * TT + (size_t)nj * 128) * DD;
    gemm_mainloop(smb, A, Bm, tid, acc);

    const int lid = tid & 31, w = tid >> 5;
    const int wm = (w >> 2) * 64, wn = (w & 3) * 32;
    const int g = lid >> 2, tg = lid & 3;
    const int rowBase = b * TT + mi * 128 + wm;
    const int colBase = b * TT + nj * 128 + wn;

    #pragma unroll
    for (int mt = 0; mt < 4; mt++) {
        float r0 = -3.0e38f, r1 = -3.0e38f;
        #pragma unroll
        for (int nt = 0; nt < 4; nt++) {
            r0 = fmaxf(r0, fmaxf(acc[mt][nt][0], acc[mt][nt][1]));
            r1 = fmaxf(r1, fmaxf(acc[mt][nt][2], acc[mt][nt][3]));
        }
        r0 = fmaxf(r0, __shfl_xor_sync(0xffffffffu, r0, 1));
        r0 = fmaxf(r0, __shfl_xor_sync(0xffffffffu, r0, 2));
        r1 = fmaxf(r1, __shfl_xor_sync(0xffffffffu, r1, 1));
        r1 = fmaxf(r1, __shfl_xor_sync(0xffffffffu, r1, 2));
        if (tg == 0) {
            atomicMax(&g_rmax[rowBase + mt * 16 + g], encf(r0));
            atomicMax(&g_rmax[rowBase + mt * 16 + g + 8], encf(r1));
        }
    }
    #pragma unroll
    for (int nt = 0; nt < 4; nt++) {
        float c0 = -3.0e38f, c1 = -3.0e38f;
        #pragma unroll
        for (int mt = 0; mt < 4; mt++) {
            c0 = fmaxf(c0, fmaxf(acc[mt][nt][0], acc[mt][nt][2]));
            c1 = fmaxf(c1, fmaxf(acc[mt][nt][1], acc[mt][nt][3]));
        }
        #pragma unroll
        for (int s = 4; s < 32; s <<= 1) {
            c0 = fmaxf(c0, __shfl_xor_sync(0xffffffffu, c0, s));
            c1 = fmaxf(c1, __shfl_xor_sync(0xffffffffu, c1, s));
        }
        if (g == 0) {
            atomicMax(&g_cmax[colBase + nt * 8 + 2 * tg], encf(c0));
            atomicMax(&g_cmax[colBase + nt * 8 + 2 * tg + 1], encf(c1));
        }
    }
}

// ---------------- k_check: certify saturation of every row/col max ------------
__global__ void k_check() {
    int i = blockIdx.x * 256 + threadIdx.x;   // 0..65535
    unsigned e = (i < BB * TT) ? g_rmax[i] : g_cmax[i - BB * TT];
    if (decf(e) < CERT_THRESH) atomicOr(&g_need_full, 1);
}

// ---------------- k_out: certified path -> means ------------------------------
__global__ void k_out_mean(float* __restrict__ out) {
    if (g_need_full) return;
    int i = blockIdx.x * 256 + threadIdx.x;   // 0..8191
    int which = i >> 12;
    int b = (i >> 8) & 15;
    int d = i & 255;
    size_t base64 = (size_t)(which * 256 + b * 16) * 4;
    float s = 0.0f;
    #pragma unroll 8
    for (int j = 0; j < 64; j++) s += g_meanpart[(base64 + j) * DD + d];
    out[i] = s * (1.0f / (float)TT);
}

// ---------------- fallback k3a: tanh + softmax over T -> weights --------------
__global__ void k3a_weights() {
    if (g_need_full == 0) return;
    __shared__ float red[256];
    int tid = threadIdx.x;
    int which = blockIdx.x >> 4;
    int b = blockIdx.x & 15;
    const unsigned* src = (which ? g_cmax : g_rmax) + b * TT;
    float* dst = g_wts + (size_t)(which * BB + b) * TT;

    float tv[8];
    #pragma unroll
    for (int i = 0; i < 8; i++) tv[i] = tanhf(decf(src[i * 256 + tid]));

    float lm = tv[0];
    #pragma unroll
    for (int i = 1; i < 8; i++) lm = fmaxf(lm, tv[i]);
    red[tid] = lm;
    __syncthreads();
    for (int s = 128; s > 0; s >>= 1) {
        if (tid < s) red[tid] = fmaxf(red[tid], red[tid + s]);
        __syncthreads();
    }
    float mx = red[0];
    __syncthreads();

    float ls = 0.0f;
    #pragma unroll
    for (int i = 0; i < 8; i++) ls += expf(tv[i] - mx);
    red[tid] = ls;
    __syncthreads();
    for (int s = 128; s > 0; s >>= 1) {
        if (tid < s) red[tid] += red[tid + s];
        __syncthreads();
    }
    float inv = 1.0f / red[0];

    #pragma unroll
    for (int i = 0; i < 8; i++) dst[i * 256 + tid] = expf(tv[i] - mx) * inv;
}

// ---------------- fallback k3b: weighted pooling partials ----------------------
__global__ void k3b_pool(const float* __restrict__ q, const float* __restrict__ a) {
    if (g_need_full == 0) return;
    __shared__ float ws[256];
    int tid = threadIdx.x;
    int slice = blockIdx.x & 7;
    int b     = (blockIdx.x >> 3) & 15;
    int which = blockIdx.x >> 7;

    ws[tid] = g_wts[(size_t)(which * BB + b) * TT + slice * 256 + tid];
    __syncthreads();

    const float* src = which ? a : q;
    const float* base = src + ((size_t)b * TT + (size_t)slice * 256) * DD + tid;
    float acc = 0.0f;
    #pragma unroll 8
    for (int t = 0; t < 256; t++) acc += ws[t] * base[(size_t)t * DD];
    g_part[(size_t)blockIdx.x * 256 + tid] = acc;
}

// ---------------- fallback k3c: reduce partials -> output ----------------------
__global__ void k3c_reduce(float* __restrict__ out) {
    if (g_need_full == 0) return;
    int i = blockIdx.x * 256 + threadIdx.x;
    int which = i >> 12;
    int b = (i >> 8) & 15;
    int d = i & 255;
    size_t pb = ((size_t)(which * BB + b) * 8) * 256 + d;
    float s = 0.0f;
    #pragma unroll
    for (int k = 0; k < 8; k++) s += g_part[pb + (size_t)k * 256];
    out[i] = s;
}

// ---------------- launch ------------------------------------------------------
extern "C" void kernel_launch(void* const* d_in, const int* in_sizes, int n_in,
                              void* d_out, int out_size) {
    int ui = 2;
    for (int i = 0; i < n_in; i++)
        if (in_sizes[i] == DD * DD) ui = i;
    const float* ptrs[3];
    int k = 0;
    for (int i = 0; i < n_in && k < 3; i++)
        if (i != ui) ptrs[k++] = (const float*)d_in[i];
    const float* q = ptrs[0];
    const float* a = ptrs[1];
    const float* U = (const float*)d_in[ui];
    float* out = (float*)d_out;

    static int attr_done = 0;
    if (!attr_done) {
        cudaFuncSetAttribute(k1_qU, cudaFuncAttributeMaxDynamicSharedMemorySize, GEMM_SMEM);
        cudaFuncSetAttribute(k2_gemm_max, cudaFuncAttributeMaxDynamicSharedMemorySize, GEMM_SMEM);
        attr_done = 1;
    }

    // converts + mean partials + aux init (merged)
    k0_convert<<<580, 256>>>(q, a, U);
    // qU (needed by certification and by fallback)
    k1_qU<<<dim3(2, 256), 256, GEMM_SMEM>>>();
    // certification slices: every row sampled on 256 cols, every col on 256 rows
    k2_gemm_max<<<dim3(2, 16, 16), 256, GEMM_SMEM>>>(0, 0, 0);
    k2_gemm_max<<<dim3(14, 2, 16), 256, GEMM_SMEM>>>(2, 0, 0);
    k_check<<<256, 256>>>();
    // certified path: write means
    k_out_mean<<<32, 256>>>(out);
    // fallback (self-disabled when certified): full exact pipeline
    k2_gemm_max<<<dim3(16, 16, 16), 256, GEMM_SMEM>>>(0, 0, 1);
    k3a_weights<<<32, 256>>>();
    k3b_pool<<<256, 256>>>(q, a);
    k3c_reduce<<<32, 256>>>(out);
    (void)out_size;
}